// round 1
// baseline (speedup 1.0000x reference)
#include <cuda_runtime.h>
#include <cstdint>

// ---------------- problem constants ----------------
#define B_    2
#define V_    5000
#define F_    6144
#define PB_   (F_/2)          // 3072 pair-blocks per mesh
#define NMESH 4               // pred0, pred1, targ0, targ1

#define LOG2E_F   1.4426950408889634f
#define K625      (-901.68440055560213f)   // -625*log2(e)
#define SI_       (1803.3688011112043f)    // -2*K625
#define SN2       5.7707801635558536f      // 4*log2(e)
#define SN_       2.4022448509f            // sqrt(SN2)

#define TILE_J   1024
#define NTILES   (F_/TILE_J)

typedef unsigned long long ull;

// ---------------- device scratch (no allocations allowed) ----------------
// pair-block layout per mesh: [pb][16]: {Cx0,Cx1, Cy0,Cy1, Cz0,Cz1, A0,A1,
//                                        Nx0,Nx1, Ny0,Ny1, Nz0,Nz1, G0,G1}
// A = K625*|C|^2 ;  N scaled by SN_ ;  G = log2(L) - SN2
__device__ float g_fd[NMESH * PB_ * 16];
__device__ float g_L [NMESH * F_];
__device__ float g_bp[6 * 24 * 3];     // [combo][i-tile][sigma]

// ---------------- f32x2 helpers ----------------
__device__ __forceinline__ ull f2fma(ull a, ull b, ull c) {
    ull d; asm("fma.rn.f32x2 %0, %1, %2, %3;" : "=l"(d) : "l"(a), "l"(b), "l"(c)); return d;
}
__device__ __forceinline__ ull f2mul(ull a, ull b) {
    ull d; asm("mul.rn.f32x2 %0, %1, %2;" : "=l"(d) : "l"(a), "l"(b)); return d;
}
__device__ __forceinline__ ull f2add(ull a, ull b) {
    ull d; asm("add.rn.f32x2 %0, %1, %2;" : "=l"(d) : "l"(a), "l"(b)); return d;
}
__device__ __forceinline__ ull splat2(float x) {
    ull d; asm("mov.b64 %0, {%1, %1};" : "=l"(d) : "f"(x)); return d;
}
__device__ __forceinline__ ull ex2x2(ull a) {
    float lo, hi, rlo, rhi; ull r;
    asm("mov.b64 {%0, %1}, %2;" : "=f"(lo), "=f"(hi) : "l"(a));
    asm("ex2.approx.f32 %0, %1;" : "=f"(rlo) : "f"(lo));
    asm("ex2.approx.f32 %0, %1;" : "=f"(rhi) : "f"(hi));
    asm("mov.b64 %0, {%1, %2};" : "=l"(r) : "f"(rlo), "f"(rhi));
    return r;
}
__device__ __forceinline__ float sum2(ull a) {
    float lo, hi;
    asm("mov.b64 {%0, %1}, %2;" : "=f"(lo), "=f"(hi) : "l"(a));
    return lo + hi;
}

// ---------------- kernel 1: per-face quantities ----------------
__global__ void mesh_kernel(const float* __restrict__ pred,
                            const float* __restrict__ targ,
                            const int*   __restrict__ faces) {
    int idx = blockIdx.x * blockDim.x + threadIdx.x;
    if (idx >= NMESH * F_) return;
    int m = idx / F_;
    int f = idx - m * F_;

    const float* Vb = (m < 2 ? pred : targ) + (m & 1) * (V_ * 3);

    int i0 = faces[3 * f + 0], i1 = faces[3 * f + 1], i2 = faces[3 * f + 2];
    float v0x = Vb[3*i0], v0y = Vb[3*i0+1], v0z = Vb[3*i0+2];
    float v1x = Vb[3*i1], v1y = Vb[3*i1+1], v1z = Vb[3*i1+2];
    float v2x = Vb[3*i2], v2y = Vb[3*i2+1], v2z = Vb[3*i2+2];

    const float third = 1.0f / 3.0f;
    float Cx = (v0x + v1x + v2x) * third;
    float Cy = (v0y + v1y + v2y) * third;
    float Cz = (v0z + v1z + v2z) * third;

    float e1x = v1x - v0x, e1y = v1y - v0y, e1z = v1z - v0z;
    float e2x = v2x - v0x, e2y = v2y - v0y, e2z = v2z - v0z;
    float Nx = 0.5f * (e1y * e2z - e1z * e2y);
    float Ny = 0.5f * (e1z * e2x - e1x * e2z);
    float Nz = 0.5f * (e1x * e2y - e1y * e2x);

    float n2 = Nx*Nx + Ny*Ny + Nz*Nz + 1e-24f;
    float L  = sqrtf(n2);
    float s  = SN_ / L;

    float A  = K625 * (Cx*Cx + Cy*Cy + Cz*Cz);
    float G  = log2f(L) - SN2;

    int base = m * (PB_ * 16) + (f >> 1) * 16 + (f & 1);
    g_fd[base + 0]  = Cx;
    g_fd[base + 2]  = Cy;
    g_fd[base + 4]  = Cz;
    g_fd[base + 6]  = A;
    g_fd[base + 8]  = Nx * s;
    g_fd[base + 10] = Ny * s;
    g_fd[base + 12] = Nz * s;
    g_fd[base + 14] = G;
    g_L[m * F_ + f] = L;
}

// ---------------- kernel 2: pairwise varifold products ----------------
// grid = (24, 6); block = 256. Each thread owns one i-face; loop over all j.
__constant__ int c_mi[6] = {0, 0, 2, 1, 1, 3};
__constant__ int c_mj[6] = {0, 2, 2, 1, 3, 3};

__global__ __launch_bounds__(256)
void pair_kernel() {
    __shared__ ulonglong2 s_tile[(TILE_J / 2) * 4];   // 32 KB
    __shared__ float s_red[8][3];

    int cmb = blockIdx.y;
    int mi = c_mi[cmb], mj = c_mj[cmb];
    int tid = threadIdx.x;
    int i = blockIdx.x * 256 + tid;

    // i-side registers (splatted)
    int ibase = mi * (PB_ * 16) + (i >> 1) * 16 + (i & 1);
    ull RX  = splat2(SI_ * g_fd[ibase + 0]);
    ull RY  = splat2(SI_ * g_fd[ibase + 2]);
    ull RZ  = splat2(SI_ * g_fd[ibase + 4]);
    ull AiD = splat2(g_fd[ibase + 6]);
    ull NX  = splat2(g_fd[ibase + 8]);
    ull NY  = splat2(g_fd[ibase + 10]);
    ull NZ  = splat2(g_fd[ibase + 12]);
    float Li = g_L[mi * F_ + i];

    ull a0 = splat2(0.0f), a1 = splat2(0.0f), a2 = splat2(0.0f);

    const float4* jsrc = (const float4*)(g_fd + (size_t)mj * (PB_ * 16));

    for (int t = 0; t < NTILES; ++t) {
        __syncthreads();
        // stage TILE_J faces (TILE_J/2 pair-blocks * 64B) into smem
        {
            float4* dst = (float4*)s_tile;
            const float4* src = jsrc + (size_t)t * (TILE_J / 2) * 4;
            #pragma unroll
            for (int k = 0; k < (TILE_J / 2) * 4 / 256; ++k)
                dst[tid + k * 256] = src[tid + k * 256];
        }
        __syncthreads();

        #pragma unroll 4
        for (int p = 0; p < TILE_J / 2; ++p) {
            ulonglong2 q0 = s_tile[p * 4 + 0];   // Cx | Cy
            ulonglong2 q1 = s_tile[p * 4 + 1];   // Cz | A
            ulonglong2 q2 = s_tile[p * 4 + 2];   // Nx | Ny
            ulonglong2 q3 = s_tile[p * 4 + 3];   // Nz | G

            // distance exponent: k*(qi+qj) - 2k*Ci.Cj  (base-2, base sigma 625)
            ull arg = f2add(AiD, q1.y);
            arg = f2fma(RX, q0.x, arg);
            arg = f2fma(RY, q0.y, arg);
            arg = f2fma(RZ, q1.x, arg);

            // normal exponent + folded log2(Lj): SN2*(ni.nj) + log2(Lj) - SN2
            ull narg = f2fma(NX, q2.x, q3.y);
            narg = f2fma(NY, q2.y, narg);
            narg = f2fma(NZ, q3.x, narg);

            ull y  = ex2x2(arg);     // exp(-625*d2)
            ull en = ex2x2(narg);    // Lj * exp(4*(ndot-1))

            ull y2  = f2mul(y,  y);
            ull y4  = f2mul(y2, y2);
            ull y8  = f2mul(y4, y4);
            ull y16 = f2mul(y8, y8);
            ull y24 = f2mul(y16, y8);
            ull y25 = f2mul(y24, y);

            a0 = f2fma(en, y4,  a0);   // sigma = 0.02  (2500  = 4*625)
            a1 = f2fma(en, y16, a1);   // sigma = 0.01  (10000 = 16*625)
            a2 = f2fma(en, y25, a2);   // sigma = 0.008 (15625 = 25*625)
        }
    }

    float r0 = Li * sum2(a0);
    float r1 = Li * sum2(a1);
    float r2 = Li * sum2(a2);

    // block reduction (deterministic)
    #pragma unroll
    for (int o = 16; o > 0; o >>= 1) {
        r0 += __shfl_down_sync(0xffffffffu, r0, o);
        r1 += __shfl_down_sync(0xffffffffu, r1, o);
        r2 += __shfl_down_sync(0xffffffffu, r2, o);
    }
    int wid = tid >> 5, lane = tid & 31;
    if (lane == 0) { s_red[wid][0] = r0; s_red[wid][1] = r1; s_red[wid][2] = r2; }
    __syncthreads();
    if (tid == 0) {
        float s0 = 0.f, s1 = 0.f, s2 = 0.f;
        #pragma unroll
        for (int w = 0; w < 8; ++w) { s0 += s_red[w][0]; s1 += s_red[w][1]; s2 += s_red[w][2]; }
        int b = (cmb * 24 + blockIdx.x) * 3;
        g_bp[b + 0] = s0; g_bp[b + 1] = s1; g_bp[b + 2] = s2;
    }
}

// ---------------- kernel 3: final combine ----------------
__global__ void combine_kernel(float* __restrict__ out) {
    __shared__ float sm[18];
    int t = threadIdx.x;
    if (t < 18) {
        int cmb = t / 3, s = t - cmb * 3;
        float acc = 0.f;
        #pragma unroll
        for (int bx = 0; bx < 24; ++bx)
            acc += g_bp[(cmb * 24 + bx) * 3 + s];
        sm[t] = acc;
    }
    __syncthreads();
    if (t == 0) {
        const float w[3] = {1.0f, 0.25f, 0.16f};
        float loss = 0.f;
        #pragma unroll
        for (int b = 0; b < 2; ++b) {
            int c0 = b * 3;
            #pragma unroll
            for (int s = 0; s < 3; ++s)
                loss += w[s] * (sm[(c0 + 0) * 3 + s]
                                - 2.0f * sm[(c0 + 1) * 3 + s]
                                + sm[(c0 + 2) * 3 + s]);
        }
        out[0] = 0.5f * loss;   // mean over B=2
    }
}

// ---------------- launch ----------------
extern "C" void kernel_launch(void* const* d_in, const int* in_sizes, int n_in,
                              void* d_out, int out_size) {
    const float* pred  = (const float*)d_in[0];
    const float* targ  = (const float*)d_in[1];
    const int*   faces = (const int*)d_in[2];
    float* out = (float*)d_out;

    mesh_kernel<<<(NMESH * F_ + 255) / 256, 256>>>(pred, targ, faces);
    dim3 grid(F_ / 256, 6, 1);
    pair_kernel<<<grid, 256>>>();
    combine_kernel<<<1, 32>>>(out);
}

// round 2
// speedup vs baseline: 1.3091x; 1.3091x over previous
#include <cuda_runtime.h>
#include <cstdint>

// ---------------- problem constants ----------------
#define B_    2
#define V_    5000
#define F_    6144
#define PB_   (F_/2)          // 3072 pair-blocks per mesh
#define NMESH 4               // pred0, pred1, targ0, targ1

#define K625      (-901.68440055560213f)   // -625*log2(e)
#define SI_       (1803.3688011112043f)    // -2*K625
#define SN2       5.7707801635558536f      // 4*log2(e)
#define SN_       2.4022448509f            // sqrt(SN2)

#define TILE_J   512
#define JCHUNKS  4
#define JPC      (F_ / JCHUNKS)            // 1536 j-faces per chunk
#define TPC      (JPC / TILE_J)            // 3 tiles per chunk

typedef unsigned long long ull;

// ---------------- device scratch (no allocations allowed) ----------------
// pair-block layout per mesh: [pb][16]: {Cx0,Cx1, Cy0,Cy1, Cz0,Cz1, A0,A1,
//                                        Nx0,Nx1, Ny0,Ny1, Nz0,Nz1, G0,G1}
// A = K625*|C|^2 ;  N scaled by SN_ ;  G = log2(L) - SN2
__device__ float g_fd[NMESH * PB_ * 16];
__device__ float g_L [NMESH * F_];
__device__ float g_bp[6 * 24 * JCHUNKS * 3];   // [combo][i-tile][jchunk][sigma]

// ---------------- f32x2 helpers ----------------
__device__ __forceinline__ ull f2fma(ull a, ull b, ull c) {
    ull d; asm("fma.rn.f32x2 %0, %1, %2, %3;" : "=l"(d) : "l"(a), "l"(b), "l"(c)); return d;
}
__device__ __forceinline__ ull f2mul(ull a, ull b) {
    ull d; asm("mul.rn.f32x2 %0, %1, %2;" : "=l"(d) : "l"(a), "l"(b)); return d;
}
__device__ __forceinline__ ull f2add(ull a, ull b) {
    ull d; asm("add.rn.f32x2 %0, %1, %2;" : "=l"(d) : "l"(a), "l"(b)); return d;
}
__device__ __forceinline__ ull splat2(float x) {
    ull d; asm("mov.b64 %0, {%1, %1};" : "=l"(d) : "f"(x)); return d;
}
__device__ __forceinline__ ull ex2x2(ull a) {
    float lo, hi, rlo, rhi; ull r;
    asm("mov.b64 {%0, %1}, %2;" : "=f"(lo), "=f"(hi) : "l"(a));
    asm("ex2.approx.f32 %0, %1;" : "=f"(rlo) : "f"(lo));
    asm("ex2.approx.f32 %0, %1;" : "=f"(rhi) : "f"(hi));
    asm("mov.b64 %0, {%1, %2};" : "=l"(r) : "f"(rlo), "f"(rhi));
    return r;
}
__device__ __forceinline__ float sum2(ull a) {
    float lo, hi;
    asm("mov.b64 {%0, %1}, %2;" : "=f"(lo), "=f"(hi) : "l"(a));
    return lo + hi;
}

// ---------------- kernel 1: per-face quantities ----------------
__global__ void mesh_kernel(const float* __restrict__ pred,
                            const float* __restrict__ targ,
                            const int*   __restrict__ faces) {
    int idx = blockIdx.x * blockDim.x + threadIdx.x;
    if (idx >= NMESH * F_) return;
    int m = idx / F_;
    int f = idx - m * F_;

    const float* Vb = (m < 2 ? pred : targ) + (m & 1) * (V_ * 3);

    int i0 = faces[3 * f + 0], i1 = faces[3 * f + 1], i2 = faces[3 * f + 2];
    float v0x = Vb[3*i0], v0y = Vb[3*i0+1], v0z = Vb[3*i0+2];
    float v1x = Vb[3*i1], v1y = Vb[3*i1+1], v1z = Vb[3*i1+2];
    float v2x = Vb[3*i2], v2y = Vb[3*i2+1], v2z = Vb[3*i2+2];

    const float third = 1.0f / 3.0f;
    float Cx = (v0x + v1x + v2x) * third;
    float Cy = (v0y + v1y + v2y) * third;
    float Cz = (v0z + v1z + v2z) * third;

    float e1x = v1x - v0x, e1y = v1y - v0y, e1z = v1z - v0z;
    float e2x = v2x - v0x, e2y = v2y - v0y, e2z = v2z - v0z;
    float Nx = 0.5f * (e1y * e2z - e1z * e2y);
    float Ny = 0.5f * (e1z * e2x - e1x * e2z);
    float Nz = 0.5f * (e1x * e2y - e1y * e2x);

    float n2 = Nx*Nx + Ny*Ny + Nz*Nz + 1e-24f;
    float L  = sqrtf(n2);
    float s  = SN_ / L;

    float A  = K625 * (Cx*Cx + Cy*Cy + Cz*Cz);
    float G  = log2f(L) - SN2;

    int base = m * (PB_ * 16) + (f >> 1) * 16 + (f & 1);
    g_fd[base + 0]  = Cx;
    g_fd[base + 2]  = Cy;
    g_fd[base + 4]  = Cz;
    g_fd[base + 6]  = A;
    g_fd[base + 8]  = Nx * s;
    g_fd[base + 10] = Ny * s;
    g_fd[base + 12] = Nz * s;
    g_fd[base + 14] = G;
    g_L[m * F_ + f] = L;
}

// ---------------- kernel 2: pairwise varifold products ----------------
// grid = (24, 6, JCHUNKS); block = 256. Thread owns one i-face; loops over
// its j-chunk (JPC faces) in TILE_J tiles staged in smem.
__constant__ int c_mi[6] = {0, 0, 2, 1, 1, 3};
__constant__ int c_mj[6] = {0, 2, 2, 1, 3, 3};

__global__ __launch_bounds__(256, 4)
void pair_kernel() {
    __shared__ ulonglong2 s_tile[(TILE_J / 2) * 4];   // 16 KB
    __shared__ float s_red[8][3];

    int cmb = blockIdx.y;
    int mi = c_mi[cmb], mj = c_mj[cmb];
    int tid = threadIdx.x;
    int i = blockIdx.x * 256 + tid;

    // i-side registers (splatted)
    int ibase = mi * (PB_ * 16) + (i >> 1) * 16 + (i & 1);
    ull RX  = splat2(SI_ * g_fd[ibase + 0]);
    ull RY  = splat2(SI_ * g_fd[ibase + 2]);
    ull RZ  = splat2(SI_ * g_fd[ibase + 4]);
    ull AiD = splat2(g_fd[ibase + 6]);
    ull NX  = splat2(g_fd[ibase + 8]);
    ull NY  = splat2(g_fd[ibase + 10]);
    ull NZ  = splat2(g_fd[ibase + 12]);
    float Li = g_L[mi * F_ + i];

    ull a0 = splat2(0.0f), a1 = splat2(0.0f), a2 = splat2(0.0f);

    const float4* jsrc = (const float4*)(g_fd + (size_t)mj * (PB_ * 16))
                       + (size_t)blockIdx.z * (JPC / 2) * 4;

    for (int t = 0; t < TPC; ++t) {
        __syncthreads();
        // stage TILE_J faces (TILE_J/2 pair-blocks * 64B) into smem
        {
            float4* dst = (float4*)s_tile;
            const float4* src = jsrc + (size_t)t * (TILE_J / 2) * 4;
            #pragma unroll
            for (int k = 0; k < (TILE_J / 2) * 4 / 256; ++k)
                dst[tid + k * 256] = src[tid + k * 256];
        }
        __syncthreads();

        #pragma unroll 4
        for (int p = 0; p < TILE_J / 2; ++p) {
            ulonglong2 q0 = s_tile[p * 4 + 0];   // Cx | Cy
            ulonglong2 q1 = s_tile[p * 4 + 1];   // Cz | A
            ulonglong2 q2 = s_tile[p * 4 + 2];   // Nx | Ny
            ulonglong2 q3 = s_tile[p * 4 + 3];   // Nz | G

            // distance exponent (base-2, base sigma 625)
            ull arg = f2add(AiD, q1.y);
            arg = f2fma(RX, q0.x, arg);
            arg = f2fma(RY, q0.y, arg);
            arg = f2fma(RZ, q1.x, arg);

            // normal exponent + folded log2(Lj)
            ull narg = f2fma(NX, q2.x, q3.y);
            narg = f2fma(NY, q2.y, narg);
            narg = f2fma(NZ, q3.x, narg);

            ull y  = ex2x2(arg);     // exp(-625*d2)
            ull en = ex2x2(narg);    // Lj * exp(4*(ndot-1))

            ull y2  = f2mul(y,  y);
            ull y4  = f2mul(y2, y2);
            ull y8  = f2mul(y4, y4);
            ull y16 = f2mul(y8, y8);
            ull y24 = f2mul(y16, y8);
            ull y25 = f2mul(y24, y);

            a0 = f2fma(en, y4,  a0);   // sigma = 0.02  (2500  = 4*625)
            a1 = f2fma(en, y16, a1);   // sigma = 0.01  (10000 = 16*625)
            a2 = f2fma(en, y25, a2);   // sigma = 0.008 (15625 = 25*625)
        }
    }

    float r0 = Li * sum2(a0);
    float r1 = Li * sum2(a1);
    float r2 = Li * sum2(a2);

    // block reduction (deterministic)
    #pragma unroll
    for (int o = 16; o > 0; o >>= 1) {
        r0 += __shfl_down_sync(0xffffffffu, r0, o);
        r1 += __shfl_down_sync(0xffffffffu, r1, o);
        r2 += __shfl_down_sync(0xffffffffu, r2, o);
    }
    int wid = tid >> 5, lane = tid & 31;
    if (lane == 0) { s_red[wid][0] = r0; s_red[wid][1] = r1; s_red[wid][2] = r2; }
    __syncthreads();
    if (tid == 0) {
        float s0 = 0.f, s1 = 0.f, s2 = 0.f;
        #pragma unroll
        for (int w = 0; w < 8; ++w) { s0 += s_red[w][0]; s1 += s_red[w][1]; s2 += s_red[w][2]; }
        int b = ((cmb * 24 + blockIdx.x) * JCHUNKS + blockIdx.z) * 3;
        g_bp[b + 0] = s0; g_bp[b + 1] = s1; g_bp[b + 2] = s2;
    }
}

// ---------------- kernel 3: final combine ----------------
__global__ void combine_kernel(float* __restrict__ out) {
    __shared__ float sm[18];
    int t = threadIdx.x;
    if (t < 18) {
        int cmb = t / 3, s = t - cmb * 3;
        float acc = 0.f;
        #pragma unroll
        for (int bx = 0; bx < 24 * JCHUNKS; ++bx)
            acc += g_bp[(cmb * 24 * JCHUNKS + bx) * 3 + s];
        sm[t] = acc;
    }
    __syncthreads();
    if (t == 0) {
        const float w[3] = {1.0f, 0.25f, 0.16f};
        float loss = 0.f;
        #pragma unroll
        for (int b = 0; b < 2; ++b) {
            int c0 = b * 3;
            #pragma unroll
            for (int s = 0; s < 3; ++s)
                loss += w[s] * (sm[(c0 + 0) * 3 + s]
                                - 2.0f * sm[(c0 + 1) * 3 + s]
                                + sm[(c0 + 2) * 3 + s]);
        }
        out[0] = 0.5f * loss;   // mean over B=2
    }
}

// ---------------- launch ----------------
extern "C" void kernel_launch(void* const* d_in, const int* in_sizes, int n_in,
                              void* d_out, int out_size) {
    const float* pred  = (const float*)d_in[0];
    const float* targ  = (const float*)d_in[1];
    const int*   faces = (const int*)d_in[2];
    float* out = (float*)d_out;

    mesh_kernel<<<(NMESH * F_ + 255) / 256, 256>>>(pred, targ, faces);
    dim3 grid(F_ / 256, 6, JCHUNKS);
    pair_kernel<<<grid, 256>>>();
    combine_kernel<<<1, 32>>>(out);
}

// round 3
// speedup vs baseline: 1.8657x; 1.4252x over previous
#include <cuda_runtime.h>
#include <cstdint>

// ---------------- problem constants ----------------
#define V_    5000
#define F_    6144
#define PB_   (F_/2)          // 3072 pair-blocks per mesh
#define NMESH 4               // pred0, pred1, targ0, targ1

#define K625      (-901.68440055560213f)   // -625*log2(e)
#define SI_       (1803.3688011112043f)    // -2*K625
#define SN2       5.7707801635558536f      // 4*log2(e)
#define SN_       2.4022448509f            // sqrt(SN2)

#define TILE_J   512
#define NJB      (F_ / TILE_J)             // 12 j-blocks
#define NTI      (F_ / 256)                // 24 i-tiles

typedef unsigned long long ull;

// ---------------- device scratch ----------------
// pair-block layout per mesh: [pb][16]: {Cx0,Cx1, Cy0,Cy1, Cz0,Cz1, A0,A1,
//                                        Nx0,Nx1, Ny0,Ny1, Nz0,Nz1, G0,G1}
__device__ float g_fd[NMESH * PB_ * 16];
__device__ float g_L [NMESH * F_];
__device__ float g_bp[6 * NTI * NJB * 3];   // [combo][i-tile][j-block][sigma]

// ---------------- f32x2 helpers ----------------
__device__ __forceinline__ ull f2fma(ull a, ull b, ull c) {
    ull d; asm("fma.rn.f32x2 %0, %1, %2, %3;" : "=l"(d) : "l"(a), "l"(b), "l"(c)); return d;
}
__device__ __forceinline__ ull f2mul(ull a, ull b) {
    ull d; asm("mul.rn.f32x2 %0, %1, %2;" : "=l"(d) : "l"(a), "l"(b)); return d;
}
__device__ __forceinline__ ull f2add(ull a, ull b) {
    ull d; asm("add.rn.f32x2 %0, %1, %2;" : "=l"(d) : "l"(a), "l"(b)); return d;
}
__device__ __forceinline__ ull splat2(float x) {
    ull d; asm("mov.b64 %0, {%1, %1};" : "=l"(d) : "f"(x)); return d;
}
__device__ __forceinline__ ull pack2(float lo, float hi) {
    ull d; asm("mov.b64 %0, {%1, %2};" : "=l"(d) : "f"(lo), "f"(hi)); return d;
}
__device__ __forceinline__ ull ex2x2(ull a) {
    float lo, hi, rlo, rhi;
    asm("mov.b64 {%0, %1}, %2;" : "=f"(lo), "=f"(hi) : "l"(a));
    asm("ex2.approx.f32 %0, %1;" : "=f"(rlo) : "f"(lo));
    asm("ex2.approx.f32 %0, %1;" : "=f"(rhi) : "f"(hi));
    return pack2(rlo, rhi);
}
__device__ __forceinline__ float sum2(ull a) {
    float lo, hi;
    asm("mov.b64 {%0, %1}, %2;" : "=f"(lo), "=f"(hi) : "l"(a));
    return lo + hi;
}

// ---------------- kernel 1: per-face quantities ----------------
__global__ void mesh_kernel(const float* __restrict__ pred,
                            const float* __restrict__ targ,
                            const int*   __restrict__ faces) {
    int idx = blockIdx.x * blockDim.x + threadIdx.x;
    if (idx >= NMESH * F_) return;
    int m = idx / F_;
    int f = idx - m * F_;

    const float* Vb = (m < 2 ? pred : targ) + (m & 1) * (V_ * 3);

    int i0 = faces[3 * f + 0], i1 = faces[3 * f + 1], i2 = faces[3 * f + 2];
    float v0x = Vb[3*i0], v0y = Vb[3*i0+1], v0z = Vb[3*i0+2];
    float v1x = Vb[3*i1], v1y = Vb[3*i1+1], v1z = Vb[3*i1+2];
    float v2x = Vb[3*i2], v2y = Vb[3*i2+1], v2z = Vb[3*i2+2];

    const float third = 1.0f / 3.0f;
    float Cx = (v0x + v1x + v2x) * third;
    float Cy = (v0y + v1y + v2y) * third;
    float Cz = (v0z + v1z + v2z) * third;

    float e1x = v1x - v0x, e1y = v1y - v0y, e1z = v1z - v0z;
    float e2x = v2x - v0x, e2y = v2y - v0y, e2z = v2z - v0z;
    float Nx = 0.5f * (e1y * e2z - e1z * e2y);
    float Ny = 0.5f * (e1z * e2x - e1x * e2z);
    float Nz = 0.5f * (e1x * e2y - e1y * e2x);

    float n2 = Nx*Nx + Ny*Ny + Nz*Nz + 1e-24f;
    float L  = sqrtf(n2);
    float s  = SN_ / L;

    float A  = K625 * (Cx*Cx + Cy*Cy + Cz*Cz);
    float G  = log2f(L) - SN2;

    int base = m * (PB_ * 16) + (f >> 1) * 16 + (f & 1);
    g_fd[base + 0]  = Cx;
    g_fd[base + 2]  = Cy;
    g_fd[base + 4]  = Cz;
    g_fd[base + 6]  = A;
    g_fd[base + 8]  = Nx * s;
    g_fd[base + 10] = Ny * s;
    g_fd[base + 12] = Nz * s;
    g_fd[base + 14] = G;
    g_L[m * F_ + f] = L;
}

// ---------------- kernel 2: pairwise varifold products ----------------
// grid = (24, 6, 12); block = 256. Thread owns one i-face; one 512-j tile
// per block. Symmetric combos keep only j-tiles at/above the diagonal.
__constant__ int c_mi[6] = {0, 0, 2, 1, 1, 3};
__constant__ int c_mj[6] = {0, 2, 2, 1, 3, 3};

struct Acc { ull a0, a1, a2; };

template <bool DIAG>
__device__ __forceinline__ void tile_loop(const ulonglong2* __restrict__ s_tile,
                                          ull RX, ull RY, ull RZ, ull AiD,
                                          ull NX, ull NY, ull NZ,
                                          int jmi,          // jb*512 - i
                                          Acc& acc) {
    ull a0 = acc.a0, a1 = acc.a1, a2 = acc.a2;
    #pragma unroll 4
    for (int p = 0; p < TILE_J / 2; ++p) {
        ulonglong2 q0 = s_tile[p * 4 + 0];   // Cx | Cy
        ulonglong2 q1 = s_tile[p * 4 + 1];   // Cz | A
        ulonglong2 q2 = s_tile[p * 4 + 2];   // Nx | Ny
        ulonglong2 q3 = s_tile[p * 4 + 3];   // Nz | G

        ull arg = f2add(AiD, q1.y);
        arg = f2fma(RX, q0.x, arg);
        arg = f2fma(RY, q0.y, arg);
        arg = f2fma(RZ, q1.x, arg);

        ull narg = f2fma(NX, q2.x, q3.y);
        narg = f2fma(NY, q2.y, narg);
        narg = f2fma(NZ, q3.x, narg);

        ull y  = ex2x2(arg);     // exp(-625*d2)
        ull en = ex2x2(narg);    // Lj * exp(4*(ndot-1))

        if (DIAG) {
            // weight: 2 if j>i else 0 (diagonal restored via Li^2 outside)
            float wlo = (2 * p + jmi     > 0) ? 2.0f : 0.0f;
            float whi = (2 * p + jmi + 1 > 0) ? 2.0f : 0.0f;
            en = f2mul(en, pack2(wlo, whi));
        }

        ull y2  = f2mul(y,  y);
        ull y4  = f2mul(y2, y2);
        ull y8  = f2mul(y4, y4);
        ull y16 = f2mul(y8, y8);
        ull y24 = f2mul(y16, y8);
        ull y25 = f2mul(y24, y);

        a0 = f2fma(en, y4,  a0);   // sigma = 0.02  (2500  = 4*625)
        a1 = f2fma(en, y16, a1);   // sigma = 0.01  (10000 = 16*625)
        a2 = f2fma(en, y25, a2);   // sigma = 0.008 (15625 = 25*625)
    }
    acc.a0 = a0; acc.a1 = a1; acc.a2 = a2;
}

__global__ __launch_bounds__(256, 4)
void pair_kernel() {
    __shared__ ulonglong2 s_tile[(TILE_J / 2) * 4];   // 16 KB
    __shared__ float s_red[8][3];

    int ti = blockIdx.x, cmb = blockIdx.y, jb = blockIdx.z;
    int mi = c_mi[cmb], mj = c_mj[cmb];
    bool sym = (mi == mj);
    int tid = threadIdx.x;
    int bslot = ((cmb * NTI + ti) * NJB + jb) * 3;

    if (sym && (2 * jb + 2 <= ti)) {       // j-tile entirely below i-tile
        if (tid == 0) { g_bp[bslot] = 0.f; g_bp[bslot+1] = 0.f; g_bp[bslot+2] = 0.f; }
        return;
    }
    bool diag = sym && (2 * jb <= ti);     // straddles the diagonal

    int i = ti * 256 + tid;

    int ibase = mi * (PB_ * 16) + (i >> 1) * 16 + (i & 1);
    ull RX  = splat2(SI_ * g_fd[ibase + 0]);
    ull RY  = splat2(SI_ * g_fd[ibase + 2]);
    ull RZ  = splat2(SI_ * g_fd[ibase + 4]);
    ull AiD = splat2(g_fd[ibase + 6]);
    ull NX  = splat2(g_fd[ibase + 8]);
    ull NY  = splat2(g_fd[ibase + 10]);
    ull NZ  = splat2(g_fd[ibase + 12]);
    float Li = g_L[mi * F_ + i];

    // stage the j-tile (512 faces = 16 KB)
    {
        float4* dst = (float4*)s_tile;
        const float4* src = (const float4*)(g_fd + (size_t)mj * (PB_ * 16))
                          + (size_t)jb * (TILE_J / 2) * 4;
        #pragma unroll
        for (int k = 0; k < (TILE_J / 2) * 4 / 256; ++k)
            dst[tid + k * 256] = src[tid + k * 256];
    }
    __syncthreads();

    Acc acc; acc.a0 = splat2(0.f); acc.a1 = splat2(0.f); acc.a2 = splat2(0.f);
    if (diag)
        tile_loop<true >(s_tile, RX, RY, RZ, AiD, NX, NY, NZ, jb * TILE_J - i, acc);
    else
        tile_loop<false>(s_tile, RX, RY, RZ, AiD, NX, NY, NZ, 0, acc);

    float mult = (sym && !diag) ? 2.0f : 1.0f;   // above-diagonal tiles count twice
    float r0 = mult * Li * sum2(acc.a0);
    float r1 = mult * Li * sum2(acc.a1);
    float r2 = mult * Li * sum2(acc.a2);
    if (diag) {                                   // K(i,i) = 1 exactly
        float d = Li * Li;
        r0 += d; r1 += d; r2 += d;
    }

    #pragma unroll
    for (int o = 16; o > 0; o >>= 1) {
        r0 += __shfl_down_sync(0xffffffffu, r0, o);
        r1 += __shfl_down_sync(0xffffffffu, r1, o);
        r2 += __shfl_down_sync(0xffffffffu, r2, o);
    }
    int wid = tid >> 5, lane = tid & 31;
    if (lane == 0) { s_red[wid][0] = r0; s_red[wid][1] = r1; s_red[wid][2] = r2; }
    __syncthreads();
    if (tid == 0) {
        float s0 = 0.f, s1 = 0.f, s2 = 0.f;
        #pragma unroll
        for (int w = 0; w < 8; ++w) { s0 += s_red[w][0]; s1 += s_red[w][1]; s2 += s_red[w][2]; }
        g_bp[bslot] = s0; g_bp[bslot + 1] = s1; g_bp[bslot + 2] = s2;
    }
}

// ---------------- kernel 3: final combine ----------------
__global__ void combine_kernel(float* __restrict__ out) {
    __shared__ float sA[6 * NTI * 3];
    __shared__ float sB[18];
    int t = threadIdx.x;
    if (t < 6 * NTI) {
        int cmb = t / NTI, ti = t - cmb * NTI;
        float a0 = 0.f, a1 = 0.f, a2 = 0.f;
        #pragma unroll
        for (int jb = 0; jb < NJB; ++jb) {
            int b = ((cmb * NTI + ti) * NJB + jb) * 3;
            a0 += g_bp[b]; a1 += g_bp[b + 1]; a2 += g_bp[b + 2];
        }
        sA[t * 3 + 0] = a0; sA[t * 3 + 1] = a1; sA[t * 3 + 2] = a2;
    }
    __syncthreads();
    if (t < 18) {
        int cmb = t / 3, s = t - cmb * 3;
        float acc = 0.f;
        #pragma unroll
        for (int ti = 0; ti < NTI; ++ti)
            acc += sA[(cmb * NTI + ti) * 3 + s];
        sB[t] = acc;
    }
    __syncthreads();
    if (t == 0) {
        const float w[3] = {1.0f, 0.25f, 0.16f};
        float loss = 0.f;
        #pragma unroll
        for (int b = 0; b < 2; ++b) {
            int c0 = b * 3;
            #pragma unroll
            for (int s = 0; s < 3; ++s)
                loss += w[s] * (sB[(c0 + 0) * 3 + s]
                                - 2.0f * sB[(c0 + 1) * 3 + s]
                                + sB[(c0 + 2) * 3 + s]);
        }
        out[0] = 0.5f * loss;   // mean over B=2
    }
}

// ---------------- launch ----------------
extern "C" void kernel_launch(void* const* d_in, const int* in_sizes, int n_in,
                              void* d_out, int out_size) {
    const float* pred  = (const float*)d_in[0];
    const float* targ  = (const float*)d_in[1];
    const int*   faces = (const int*)d_in[2];
    float* out = (float*)d_out;

    mesh_kernel<<<(NMESH * F_ + 255) / 256, 256>>>(pred, targ, faces);
    dim3 grid(NTI, 6, NJB);
    pair_kernel<<<grid, 256>>>();
    combine_kernel<<<1, 192>>>(out);
}

// round 4
// speedup vs baseline: 1.9110x; 1.0243x over previous
#include <cuda_runtime.h>
#include <cstdint>

// ---------------- problem constants ----------------
#define V_    5000
#define F_    6144
#define PB_   (F_/2)          // 3072 pair-blocks per mesh
#define NMESH 4               // pred0, pred1, targ0, targ1

#define K625      (-901.68440055560213f)   // -625*log2(e)
#define SI_       (1803.3688011112043f)    // -2*K625
#define SN2       5.7707801635558536f      // 4*log2(e)
#define SN_       2.4022448509f            // sqrt(SN2)

#define TILE_J   512
#define NJB      (F_ / TILE_J)             // 12 j-blocks
#define ITILE    512
#define NTI      (F_ / ITILE)              // 12 i-tiles (512 i each, 2 per thread)

typedef unsigned long long ull;

// ---------------- device scratch ----------------
// pair-block layout per mesh: [pb][16]: {Cx0,Cx1, Cy0,Cy1, Cz0,Cz1, A0,A1,
//                                        Nx0,Nx1, Ny0,Ny1, Nz0,Nz1, G0,G1}
__device__ float g_fd[NMESH * PB_ * 16];
__device__ float g_L [NMESH * F_];
__device__ float g_bp[6 * NTI * NJB * 3];   // [combo][i-tile][j-block][sigma]

// ---------------- f32x2 helpers ----------------
__device__ __forceinline__ ull f2fma(ull a, ull b, ull c) {
    ull d; asm("fma.rn.f32x2 %0, %1, %2, %3;" : "=l"(d) : "l"(a), "l"(b), "l"(c)); return d;
}
__device__ __forceinline__ ull f2mul(ull a, ull b) {
    ull d; asm("mul.rn.f32x2 %0, %1, %2;" : "=l"(d) : "l"(a), "l"(b)); return d;
}
__device__ __forceinline__ ull f2add(ull a, ull b) {
    ull d; asm("add.rn.f32x2 %0, %1, %2;" : "=l"(d) : "l"(a), "l"(b)); return d;
}
__device__ __forceinline__ ull splat2(float x) {
    ull d; asm("mov.b64 %0, {%1, %1};" : "=l"(d) : "f"(x)); return d;
}
__device__ __forceinline__ ull pack2(float lo, float hi) {
    ull d; asm("mov.b64 %0, {%1, %2};" : "=l"(d) : "f"(lo), "f"(hi)); return d;
}
__device__ __forceinline__ ull ex2x2(ull a) {
    float lo, hi, rlo, rhi;
    asm("mov.b64 {%0, %1}, %2;" : "=f"(lo), "=f"(hi) : "l"(a));
    asm("ex2.approx.f32 %0, %1;" : "=f"(rlo) : "f"(lo));
    asm("ex2.approx.f32 %0, %1;" : "=f"(rhi) : "f"(hi));
    return pack2(rlo, rhi);
}
__device__ __forceinline__ float sum2(ull a) {
    float lo, hi;
    asm("mov.b64 {%0, %1}, %2;" : "=f"(lo), "=f"(hi) : "l"(a));
    return lo + hi;
}

// ---------------- kernel 1: per-face quantities ----------------
__global__ void mesh_kernel(const float* __restrict__ pred,
                            const float* __restrict__ targ,
                            const int*   __restrict__ faces) {
    int idx = blockIdx.x * blockDim.x + threadIdx.x;
    if (idx >= NMESH * F_) return;
    int m = idx / F_;
    int f = idx - m * F_;

    const float* Vb = (m < 2 ? pred : targ) + (m & 1) * (V_ * 3);

    int i0 = faces[3 * f + 0], i1 = faces[3 * f + 1], i2 = faces[3 * f + 2];
    float v0x = Vb[3*i0], v0y = Vb[3*i0+1], v0z = Vb[3*i0+2];
    float v1x = Vb[3*i1], v1y = Vb[3*i1+1], v1z = Vb[3*i1+2];
    float v2x = Vb[3*i2], v2y = Vb[3*i2+1], v2z = Vb[3*i2+2];

    const float third = 1.0f / 3.0f;
    float Cx = (v0x + v1x + v2x) * third;
    float Cy = (v0y + v1y + v2y) * third;
    float Cz = (v0z + v1z + v2z) * third;

    float e1x = v1x - v0x, e1y = v1y - v0y, e1z = v1z - v0z;
    float e2x = v2x - v0x, e2y = v2y - v0y, e2z = v2z - v0z;
    float Nx = 0.5f * (e1y * e2z - e1z * e2y);
    float Ny = 0.5f * (e1z * e2x - e1x * e2z);
    float Nz = 0.5f * (e1x * e2y - e1y * e2x);

    float n2 = Nx*Nx + Ny*Ny + Nz*Nz + 1e-24f;
    float L  = sqrtf(n2);
    float s  = SN_ / L;

    float A  = K625 * (Cx*Cx + Cy*Cy + Cz*Cz);
    float G  = log2f(L) - SN2;

    int base = m * (PB_ * 16) + (f >> 1) * 16 + (f & 1);
    g_fd[base + 0]  = Cx;
    g_fd[base + 2]  = Cy;
    g_fd[base + 4]  = Cz;
    g_fd[base + 6]  = A;
    g_fd[base + 8]  = Nx * s;
    g_fd[base + 10] = Ny * s;
    g_fd[base + 12] = Nz * s;
    g_fd[base + 14] = G;
    g_L[m * F_ + f] = L;
}

// ---------------- kernel 2: pairwise varifold products ----------------
// grid = (12, 6, 12); block = 256. Each thread owns TWO i-faces (i, i+256)
// within a 512-i tile; one 512-j tile staged in smem per block.
__constant__ int c_mi[6] = {0, 0, 2, 1, 1, 3};
__constant__ int c_mj[6] = {0, 2, 2, 1, 3, 3};

struct IFace { ull RX, RY, RZ, AiD, NX, NY, NZ; };
struct Acc3  { ull a0, a1, a2; };

template <bool DIAG>
__device__ __forceinline__ void tile_loop2(const ulonglong2* __restrict__ s_tile,
                                           const IFace& I0, const IFace& I1,
                                           int jmi0, int jmi1,
                                           Acc3& A0, Acc3& A1) {
    ull a00 = A0.a0, a01 = A0.a1, a02 = A0.a2;
    ull a10 = A1.a0, a11 = A1.a1, a12 = A1.a2;
    #pragma unroll 2
    for (int p = 0; p < TILE_J / 2; ++p) {
        ulonglong2 q0 = s_tile[p * 4 + 0];   // Cx | Cy
        ulonglong2 q1 = s_tile[p * 4 + 1];   // Cz | A
        ulonglong2 q2 = s_tile[p * 4 + 2];   // Nx | Ny
        ulonglong2 q3 = s_tile[p * 4 + 3];   // Nz | G

        // -------- chain 0 --------
        ull arg0 = f2add(I0.AiD, q1.y);
        arg0 = f2fma(I0.RX, q0.x, arg0);
        arg0 = f2fma(I0.RY, q0.y, arg0);
        arg0 = f2fma(I0.RZ, q1.x, arg0);
        ull narg0 = f2fma(I0.NX, q2.x, q3.y);
        narg0 = f2fma(I0.NY, q2.y, narg0);
        narg0 = f2fma(I0.NZ, q3.x, narg0);

        // -------- chain 1 --------
        ull arg1 = f2add(I1.AiD, q1.y);
        arg1 = f2fma(I1.RX, q0.x, arg1);
        arg1 = f2fma(I1.RY, q0.y, arg1);
        arg1 = f2fma(I1.RZ, q1.x, arg1);
        ull narg1 = f2fma(I1.NX, q2.x, q3.y);
        narg1 = f2fma(I1.NY, q2.y, narg1);
        narg1 = f2fma(I1.NZ, q3.x, narg1);

        ull y0  = ex2x2(arg0);
        ull en0 = ex2x2(narg0);
        ull y1  = ex2x2(arg1);
        ull en1 = ex2x2(narg1);

        if (DIAG) {
            float w0lo = (2 * p + jmi0     > 0) ? 2.0f : 0.0f;
            float w0hi = (2 * p + jmi0 + 1 > 0) ? 2.0f : 0.0f;
            en0 = f2mul(en0, pack2(w0lo, w0hi));
            float w1lo = (2 * p + jmi1     > 0) ? 2.0f : 0.0f;
            float w1hi = (2 * p + jmi1 + 1 > 0) ? 2.0f : 0.0f;
            en1 = f2mul(en1, pack2(w1lo, w1hi));
        }

        // -------- powers + accum, chain 0 --------
        {
            ull y2  = f2mul(y0, y0);
            ull y4  = f2mul(y2, y2);
            ull y8  = f2mul(y4, y4);
            ull y16 = f2mul(y8, y8);
            ull y24 = f2mul(y16, y8);
            ull y25 = f2mul(y24, y0);
            a00 = f2fma(en0, y4,  a00);
            a01 = f2fma(en0, y16, a01);
            a02 = f2fma(en0, y25, a02);
        }
        // -------- powers + accum, chain 1 --------
        {
            ull y2  = f2mul(y1, y1);
            ull y4  = f2mul(y2, y2);
            ull y8  = f2mul(y4, y4);
            ull y16 = f2mul(y8, y8);
            ull y24 = f2mul(y16, y8);
            ull y25 = f2mul(y24, y1);
            a10 = f2fma(en1, y4,  a10);
            a11 = f2fma(en1, y16, a11);
            a12 = f2fma(en1, y25, a12);
        }
    }
    A0.a0 = a00; A0.a1 = a01; A0.a2 = a02;
    A1.a0 = a10; A1.a1 = a11; A1.a2 = a12;
}

__device__ __forceinline__ void load_iface(int m, int i, IFace& I) {
    int b = m * (PB_ * 16) + (i >> 1) * 16 + (i & 1);
    I.RX  = splat2(SI_ * g_fd[b + 0]);
    I.RY  = splat2(SI_ * g_fd[b + 2]);
    I.RZ  = splat2(SI_ * g_fd[b + 4]);
    I.AiD = splat2(g_fd[b + 6]);
    I.NX  = splat2(g_fd[b + 8]);
    I.NY  = splat2(g_fd[b + 10]);
    I.NZ  = splat2(g_fd[b + 12]);
}

__global__ __launch_bounds__(256, 4)
void pair_kernel() {
    __shared__ ulonglong2 s_tile[(TILE_J / 2) * 4];   // 16 KB
    __shared__ float s_red[8][3];

    int ti = blockIdx.x, cmb = blockIdx.y, jb = blockIdx.z;
    int mi = c_mi[cmb], mj = c_mj[cmb];
    bool sym = (mi == mj);
    int tid = threadIdx.x;
    int bslot = ((cmb * NTI + ti) * NJB + jb) * 3;

    if (sym && (jb < ti)) {                 // j-tile entirely below i-tile
        if (tid == 0) { g_bp[bslot] = 0.f; g_bp[bslot+1] = 0.f; g_bp[bslot+2] = 0.f; }
        return;
    }
    bool diag = sym && (jb == ti);

    int i0 = ti * ITILE + tid;
    int i1 = i0 + 256;

    IFace I0, I1;
    load_iface(mi, i0, I0);
    load_iface(mi, i1, I1);
    float Li0 = g_L[mi * F_ + i0];
    float Li1 = g_L[mi * F_ + i1];

    // stage the j-tile (512 faces = 16 KB)
    {
        float4* dst = (float4*)s_tile;
        const float4* src = (const float4*)(g_fd + (size_t)mj * (PB_ * 16))
                          + (size_t)jb * (TILE_J / 2) * 4;
        #pragma unroll
        for (int k = 0; k < (TILE_J / 2) * 4 / 256; ++k)
            dst[tid + k * 256] = src[tid + k * 256];
    }
    __syncthreads();

    Acc3 A0, A1;
    A0.a0 = splat2(0.f); A0.a1 = splat2(0.f); A0.a2 = splat2(0.f);
    A1.a0 = splat2(0.f); A1.a1 = splat2(0.f); A1.a2 = splat2(0.f);

    if (diag)
        tile_loop2<true >(s_tile, I0, I1, -tid, -tid - 256, A0, A1);
    else
        tile_loop2<false>(s_tile, I0, I1, 0, 0, A0, A1);

    float mult = (sym && !diag) ? 2.0f : 1.0f;
    float r0 = mult * (Li0 * sum2(A0.a0) + Li1 * sum2(A1.a0));
    float r1 = mult * (Li0 * sum2(A0.a1) + Li1 * sum2(A1.a1));
    float r2 = mult * (Li0 * sum2(A0.a2) + Li1 * sum2(A1.a2));
    if (diag) {                              // K(i,i) = 1 exactly
        float d = Li0 * Li0 + Li1 * Li1;
        r0 += d; r1 += d; r2 += d;
    }

    #pragma unroll
    for (int o = 16; o > 0; o >>= 1) {
        r0 += __shfl_down_sync(0xffffffffu, r0, o);
        r1 += __shfl_down_sync(0xffffffffu, r1, o);
        r2 += __shfl_down_sync(0xffffffffu, r2, o);
    }
    int wid = tid >> 5, lane = tid & 31;
    if (lane == 0) { s_red[wid][0] = r0; s_red[wid][1] = r1; s_red[wid][2] = r2; }
    __syncthreads();
    if (tid == 0) {
        float s0 = 0.f, s1 = 0.f, s2 = 0.f;
        #pragma unroll
        for (int w = 0; w < 8; ++w) { s0 += s_red[w][0]; s1 += s_red[w][1]; s2 += s_red[w][2]; }
        g_bp[bslot] = s0; g_bp[bslot + 1] = s1; g_bp[bslot + 2] = s2;
    }
}

// ---------------- kernel 3: final combine ----------------
__global__ void combine_kernel(float* __restrict__ out) {
    __shared__ float sA[6 * NTI * 3];
    __shared__ float sB[18];
    int t = threadIdx.x;
    if (t < 6 * NTI) {
        int cmb = t / NTI, ti = t - cmb * NTI;
        float a0 = 0.f, a1 = 0.f, a2 = 0.f;
        #pragma unroll
        for (int jb = 0; jb < NJB; ++jb) {
            int b = ((cmb * NTI + ti) * NJB + jb) * 3;
            a0 += g_bp[b]; a1 += g_bp[b + 1]; a2 += g_bp[b + 2];
        }
        sA[t * 3 + 0] = a0; sA[t * 3 + 1] = a1; sA[t * 3 + 2] = a2;
    }
    __syncthreads();
    if (t < 18) {
        int cmb = t / 3, s = t - cmb * 3;
        float acc = 0.f;
        #pragma unroll
        for (int ti = 0; ti < NTI; ++ti)
            acc += sA[(cmb * NTI + ti) * 3 + s];
        sB[t] = acc;
    }
    __syncthreads();
    if (t == 0) {
        const float w[3] = {1.0f, 0.25f, 0.16f};
        float loss = 0.f;
        #pragma unroll
        for (int b = 0; b < 2; ++b) {
            int c0 = b * 3;
            #pragma unroll
            for (int s = 0; s < 3; ++s)
                loss += w[s] * (sB[(c0 + 0) * 3 + s]
                                - 2.0f * sB[(c0 + 1) * 3 + s]
                                + sB[(c0 + 2) * 3 + s]);
        }
        out[0] = 0.5f * loss;   // mean over B=2
    }
}

// ---------------- launch ----------------
extern "C" void kernel_launch(void* const* d_in, const int* in_sizes, int n_in,
                              void* d_out, int out_size) {
    const float* pred  = (const float*)d_in[0];
    const float* targ  = (const float*)d_in[1];
    const int*   faces = (const int*)d_in[2];
    float* out = (float*)d_out;

    mesh_kernel<<<(NMESH * F_ + 255) / 256, 256>>>(pred, targ, faces);
    dim3 grid(NTI, 6, NJB);
    pair_kernel<<<grid, 256>>>();
    combine_kernel<<<1, 192>>>(out);
}